// round 9
// baseline (speedup 1.0000x reference)
#include <cuda_runtime.h>

// Depthwise separable 4x4 blur, filter [1,3,3,1] (x) [1,3,3,1] / 64.
// Input  (8, 256, 64, 512) fp32, W-pad circular(1), H-pad reflect(1).
// Output (8, 256, 63, 511) fp32.
//
// R9 = R3 (4-deep register prefetch ring, 99.5us) with:
//  1. shuffle-sourced B taps: src cols 4t+4..4t+6 are thread t+1's A.x/y/z,
//     fetched via 3 __shfl_down_sync; only lane 31 keeps a real B load.
//     Halves read LDG instructions / L1 read wavefronts (DRAM bytes same).
//  2. __stcs streaming stores: evict-first writes keep L2 for read reuse.

#define W   512
#define H   64
#define OW  511
#define OH  63

__device__ __forceinline__ float4 f4_vblur(const float4& a, const float4& b,
                                           const float4& c, const float4& d)
{
    float4 r;
    r.x = ((a.x + d.x) + 3.0f * (b.x + c.x)) * (1.0f / 64.0f);
    r.y = ((a.y + d.y) + 3.0f * (b.y + c.y)) * (1.0f / 64.0f);
    r.z = ((a.z + d.z) + 3.0f * (b.z + c.z)) * (1.0f / 64.0f);
    r.w = ((a.w + d.w) + 3.0f * (b.w + c.w)) * (1.0f / 64.0f);
    return r;
}

__global__ __launch_bounds__(128) void Blur_49976239456711_kernel(
    const float* __restrict__ in, float* __restrict__ out)
{
    const int t    = threadIdx.x;          // 0..127, owns src cols 4t..4t+3
    const int lane = t & 31;
    const int img  = blockIdx.x;           // 0..2047

    const float* __restrict__ src = in  + (size_t)img * (H * W);
    float*       __restrict__ dst = out + (size_t)img * (OH * OW);

    const int cA = 4 * t;
    const int cB = (4 * t + 4) & (W - 1);  // lane-31 B base (t=127 wraps to 0)
    const bool ldB = (lane == 31);

    // Horizontal blur for outputs ox = 4t+1..4t+4. Needs src cols 4t..4t+6;
    // cols 4t+4..4t+6 come from lane+1's A via shuffle (lane 31: real load).
    auto hblur_sh = [&](const float4& A, const float4& B31) -> float4 {
        float bx = __shfl_down_sync(0xffffffffu, A.x, 1);
        float by = __shfl_down_sync(0xffffffffu, A.y, 1);
        float bz = __shfl_down_sync(0xffffffffu, A.z, 1);
        if (ldB) { bx = B31.x; by = B31.y; bz = B31.z; }
        float4 r;
        r.x = (A.x + A.w) + 3.0f * (A.y + A.z);
        r.y = (A.y + bx)  + 3.0f * (A.z + A.w);
        r.z = (A.z + by)  + 3.0f * (A.w + bx);
        r.w = (A.w + bz)  + 3.0f * (bx + by);
        return r;
    };

    const int  ox0  = 4 * t + 1;
    const bool full = (t < 127);            // t=127 covers ox 509,510,(skip),0
    auto store4 = [&](int oy, const float4& v) {
        float* row = dst + oy * OW;
        __stcs(row + ox0,     v.x);
        __stcs(row + ox0 + 1, v.y);
        if (full) {
            __stcs(row + ox0 + 2, v.z);
            __stcs(row + ox0 + 3, v.w);
        } else {
            __stcs(row + 0, v.w);           // circular wrap: ox=0
        }
    };

    // ── 4-deep prefetch ring: slot s holds src row (loaded 4 iters ahead) ──
    float4 pa[4], pb[4];

    auto issue = [&](int y, int s) {
        pa[s] = __ldg(reinterpret_cast<const float4*>(src + y * W + cA));
        if (ldB)
            pb[s] = __ldg(reinterpret_cast<const float4*>(src + y * W + cB));
    };

    // Prologue: prefetch rows 2..5 (consumed at oy = 0..3), plus rows 1,0 for
    // the initial window (reflect: padded 0->src 1, padded 1->src 0, padded 2->src 1).
    issue(2, 0); issue(3, 1); issue(4, 2); issue(5, 3);

    float4 hb0, hb1, hb2, hb3;
    {
        const float4 A1 = __ldg(reinterpret_cast<const float4*>(src + 1 * W + cA));
        float4 B1 = make_float4(0.f, 0.f, 0.f, 0.f);
        if (ldB) B1 = __ldg(reinterpret_cast<const float4*>(src + 1 * W + cB));
        const float4 A0 = __ldg(reinterpret_cast<const float4*>(src + 0 * W + cA));
        float4 B0 = make_float4(0.f, 0.f, 0.f, 0.f);
        if (ldB) B0 = __ldg(reinterpret_cast<const float4*>(src + 0 * W + cB));

        hb0 = hblur_sh(A1, B1);   // HB[padded 0] = src row 1
        hb1 = hblur_sh(A0, B0);   // HB[padded 1] = src row 0
        hb2 = hb0;                // HB[padded 2] = src row 1
    }

    // Main loop: output oy consumes src row oy+2 from slot (oy&3), refills
    // that slot with src row oy+6. unroll 4 keeps ring indices static.
    #pragma unroll 4
    for (int oy = 0; oy < OH - 1; ++oy) {          // oy = 0..61
        const int s = oy & 3;
        hb3 = hblur_sh(pa[s], pb[s]);              // src row oy+2
        const int ny = oy + 6;
        if (ny < H) issue(ny, s);
        store4(oy, f4_vblur(hb0, hb1, hb2, hb3));
        hb0 = hb1; hb1 = hb2; hb2 = hb3;
    }

    // oy = 62: padded row 65 reflects to src row 62 (hot in cache — reload)
    {
        const float4 A = __ldg(reinterpret_cast<const float4*>(src + 62 * W + cA));
        float4 B = make_float4(0.f, 0.f, 0.f, 0.f);
        if (ldB) B = __ldg(reinterpret_cast<const float4*>(src + 62 * W + cB));
        hb3 = hblur_sh(A, B);
        store4(OH - 1, f4_vblur(hb0, hb1, hb2, hb3));
    }
}

extern "C" void kernel_launch(void* const* d_in, const int* in_sizes, int n_in,
                              void* d_out, int out_size)
{
    const float* h = (const float*)d_in[0];
    float* out = (float*)d_out;

    const int n_img = 8 * 256;              // 2048 images of 64x512
    Blur_49976239456711_kernel<<<n_img, 128>>>(h, out);
}